// round 2
// baseline (speedup 1.0000x reference)
#include <cuda_runtime.h>
#include <cstdint>

// Problem constants
#define NB   4
#define IC   3
#define OC   16
#define IDIM 128
#define ODIM 127
#define H_STR   128
#define D_STR   (128*128)         // 16384
#define C_STR   (128*128*128)     // 2097152
#define O_HSTR  127
#define O_DSTR  (127*127)         // 16129
#define O_CSTR  (127*127*127)     // 2048383

typedef unsigned long long ull;

__device__ float2 g_fw[24][16];   // [tap = ic*8+kd*4+kh*2+kw][oc], value duplicated (w,w)
__device__ float2 g_fb[16];       // duplicated (b,b)

__device__ __forceinline__ ull fma2(ull a, ull b, ull c) {
    ull d;
    asm("fma.rn.f32x2 %0, %1, %2, %3;" : "=l"(d) : "l"(a), "l"(b), "l"(c));
    return d;
}
__device__ __forceinline__ ull pack2(float lo, float hi) {
    ull d;
    asm("mov.b64 %0, {%1, %2};" : "=l"(d) : "f"(lo), "f"(hi));
    return d;
}
__device__ __forceinline__ float2 unpack2(ull v) {
    float2 r;
    asm("mov.b64 {%0, %1}, %2;" : "=f"(r.x), "=f"(r.y) : "l"(v));
    return r;
}

// Fold ConvTranspose(k3,s2,p1)+AvgPool(2) -> 2x2x2 conv weight, with scales.
// Folded axis index 0 <- original taps {1,2} summed ; index 1 <- tap {0}.
__global__ void prep_kernel(const float* __restrict__ cw,
                            const float* __restrict__ cb,
                            const float* __restrict__ eb) {
    int t = threadIdx.x;
    if (t >= 24 * 16) return;
    int oc  = t & 15;
    int tap = t >> 4;                 // 0..23
    int kw = tap & 1, kh = (tap >> 1) & 1, kd = (tap >> 2) & 1, ic = tap >> 3;
    // S(0) = {1,2} -> [1,3) ; S(1) = {0} -> [0,1)
    int dlo = kd ? 0 : 1, dhi = kd ? 1 : 3;
    int hlo = kh ? 0 : 1, hhi = kh ? 1 : 3;
    int wlo = kw ? 0 : 1, whi = kw ? 1 : 3;
    const float* w = cw + (ic * 16 + oc) * 27;   // cw layout (ic, oc, 3,3,3)
    float s = 0.f;
    for (int i = dlo; i < dhi; i++)
        for (int j = hlo; j < hhi; j++)
            for (int k = wlo; k < whi; k++)
                s += w[i * 9 + j * 3 + k];
    s *= 0.0625f;                                 // SCALE1*SCALE2*0.125
    g_fw[tap][oc] = make_float2(s, s);
    if (t < 16) {
        float b = cb[t] * 0.5f + eb[t];          // (cb*SCALE1 + ext)*SCALE2
        g_fb[t] = make_float2(b, b);
    }
}

// Each thread: 4 consecutive w-outputs (2 f32x2 pairs) x all 16 oc at one (n,od,oh).
// Block = 32 (w) x 8 (oh). Grid = (16 oh-tiles, 127 od, 4 n).
__global__ void __launch_bounds__(256, 2)
conv_main(const float* __restrict__ x, float* __restrict__ out) {
    __shared__ float2 smw[24 * 16];
    __shared__ float2 smb[16];

    int tid = threadIdx.y * 32 + threadIdx.x;
    {
        const float2* gw = (const float2*)g_fw;
        for (int i = tid; i < 24 * 16; i += 256) smw[i] = gw[i];
        if (tid < 16) smb[tid] = g_fb[tid];
    }
    __syncthreads();

    int oh = blockIdx.x * 8 + threadIdx.y;
    if (oh >= ODIM) return;
    int od = blockIdx.y;
    int n  = blockIdx.z;
    int wb = threadIdx.x * 4;                 // 0..124
    bool full = (wb != 124);                  // wb==124 -> w=127 is out of range

    ull acc[16][2];
#pragma unroll
    for (int oc = 0; oc < 16; oc++) {
        ull b = *(const ull*)&smb[oc];
        acc[oc][0] = b;
        acc[oc][1] = b;
    }

    const float* xn = x + (size_t)n * IC * C_STR;

#pragma unroll
    for (int ic = 0; ic < IC; ic++) {
#pragma unroll
        for (int kd = 0; kd < 2; kd++) {
#pragma unroll
            for (int kh = 0; kh < 2; kh++) {
                const float* row = xn + (size_t)ic * C_STR
                                      + (size_t)(od + kd) * D_STR
                                      + (size_t)(oh + kh) * H_STR;
                float4 v = *(const float4*)(row + wb);       // 16B aligned
                float x4 = full ? row[wb + 4] : 0.f;
                ull p0 = pack2(v.x, v.y);                    // kw=0 pairs
                ull p1 = pack2(v.z, v.w);
                ull q0 = pack2(v.y, v.z);                    // kw=1 pairs
                ull q1 = pack2(v.w, x4);
                int base = (((ic * 2 + kd) * 2 + kh) * 2) * 16;
#pragma unroll
                for (int oc = 0; oc < 16; oc++) {
                    ull w0 = *(const ull*)&smw[base + oc];        // kw=0 weight (dup)
                    ull w1 = *(const ull*)&smw[base + 16 + oc];   // kw=1 weight (dup)
                    acc[oc][0] = fma2(p0, w0, acc[oc][0]);
                    acc[oc][1] = fma2(p1, w0, acc[oc][1]);
                    acc[oc][0] = fma2(q0, w1, acc[oc][0]);
                    acc[oc][1] = fma2(q1, w1, acc[oc][1]);
                }
            }
        }
    }

    float* op = out + (size_t)n * OC * O_CSTR
                    + (size_t)od * O_DSTR
                    + (size_t)oh * O_HSTR + wb;
#pragma unroll
    for (int oc = 0; oc < 16; oc++) {
        float2 a = unpack2(acc[oc][0]);
        float2 b = unpack2(acc[oc][1]);
        op[0] = a.x;
        op[1] = a.y;
        op[2] = b.x;
        if (full) op[3] = b.y;
        op += O_CSTR;
    }
}

extern "C" void kernel_launch(void* const* d_in, const int* in_sizes, int n_in,
                              void* d_out, int out_size) {
    const float* x  = (const float*)d_in[0];
    const float* cw = (const float*)d_in[1];
    const float* cb = (const float*)d_in[2];
    const float* eb = (const float*)d_in[3];
    float* out = (float*)d_out;

    prep_kernel<<<1, 24 * 16>>>(cw, cb, eb);

    dim3 block(32, 8, 1);
    dim3 grid(16, ODIM, NB);    // 16 oh-tiles of 8, 127 od, 4 batches
    conv_main<<<grid, block>>>(x, out);
}